// round 4
// baseline (speedup 1.0000x reference)
#include <cuda_runtime.h>
#include <cstdint>

#define BATCH   2048
#define INSZ    40960
#define KC      64
#define NSTAGE  (INSZ / KC)        // 640
#define ASTRIDE 68                 // 64 + 4 pad (floats)
#define BSTRIDE 68
#define A_FLOATS (128 * ASTRIDE)   // 8704
#define B_FLOATS (64 * BSTRIDE)    // 4352
#define BUF_FLOATS (A_FLOATS + B_FLOATS)      // 13056
#define SMEM_BYTES (2 * BUF_FLOATS * 4)       // 104448

__device__ float g_comb[(size_t)BATCH * 512];   // [m][512] combined crelu features

__device__ __forceinline__ float crelu(float x) { return fminf(fmaxf(x, 0.f), 1.f); }

__device__ __forceinline__ uint32_t f2tf32(float x) {
    uint32_t r;
    asm("cvt.rna.tf32.f32 %0, %1;" : "=r"(r) : "f"(x));
    return r;
}

__device__ __forceinline__ void mma8(float& c0, float& c1, float& c2, float& c3,
                                     uint32_t a0, uint32_t a1, uint32_t a2, uint32_t a3,
                                     uint32_t b0, uint32_t b1) {
    asm volatile(
        "mma.sync.aligned.m16n8k8.row.col.f32.tf32.tf32.f32 "
        "{%0,%1,%2,%3}, {%4,%5,%6,%7}, {%8,%9}, {%0,%1,%2,%3};"
        : "+f"(c0), "+f"(c1), "+f"(c2), "+f"(c3)
        : "r"(a0), "r"(a1), "r"(a2), "r"(a3), "r"(b0), "r"(b1));
}

// ================= Kernel 1: feature transformer GEMM (tf32 mma.sync) ==========
// C[2048,256] = X[2048,40960] @ W[256,40960]^T, fused bias + crelu, per perspective.
// grid = 128: bid -> persp (bid>>6), mt ((bid>>2)&15), nt (bid&3). block = 256.
__global__ void __launch_bounds__(256, 1)
ft_kernel(const float* __restrict__ xp, const float* __restrict__ xo,
          const float* __restrict__ wp, const float* __restrict__ wo,
          const float* __restrict__ b1p, const float* __restrict__ b1o)
{
    extern __shared__ float sm[];
    const int tid  = threadIdx.x, lane = tid & 31, wid = tid >> 5;
    const int bid  = blockIdx.x;
    const int persp = bid >> 6, mt = (bid >> 2) & 15, nt = bid & 3;
    const float* __restrict__ X    = persp ? xo : xp;
    const float* __restrict__ W    = persp ? wo : wp;
    const float* __restrict__ bias = persp ? b1o : b1p;
    const int m0 = mt * 128, n0 = nt * 64;

    // ---- producer addressing: A = 2048 float4 (128 rows x 16 quads), 8/thread
    //                           B = 1024 float4 ( 64 rows x 16 quads), 4/thread
    const float* aptr[8]; int asm_off[8];
    const float* bptr[4]; int bsm_off[4];
    #pragma unroll
    for (int i = 0; i < 8; i++) {
        int f = tid + i * 256, r = f >> 4, q = f & 15;
        aptr[i]   = X + (size_t)(m0 + r) * INSZ + q * 4;
        asm_off[i] = r * ASTRIDE + q * 4;
    }
    #pragma unroll
    for (int i = 0; i < 4; i++) {
        int f = tid + i * 256, r = f >> 4, q = f & 15;
        bptr[i]   = W + (size_t)(n0 + r) * INSZ + q * 4;
        bsm_off[i] = r * BSTRIDE + q * 4;
    }

    const int wm = (wid >> 1) * 32;   // warp m offset in tile (0,32,64,96)
    const int wn = (wid & 1) * 32;    // warp n offset in tile (0,32)

    float acc[2][4][4];
    #pragma unroll
    for (int i = 0; i < 2; i++)
        #pragma unroll
        for (int j = 0; j < 4; j++)
            #pragma unroll
            for (int k = 0; k < 4; k++) acc[i][j][k] = 0.f;

    float4 ra[8], rb[4];

    // prologue: load stage 0
    #pragma unroll
    for (int i = 0; i < 8; i++) ra[i] = *reinterpret_cast<const float4*>(aptr[i]);
    #pragma unroll
    for (int i = 0; i < 4; i++) rb[i] = *reinterpret_cast<const float4*>(bptr[i]);
    {
        float* s0 = sm;
        #pragma unroll
        for (int i = 0; i < 8; i++) {
            uint32_t* p = reinterpret_cast<uint32_t*>(s0 + asm_off[i]);
            p[0] = f2tf32(ra[i].x); p[1] = f2tf32(ra[i].y);
            p[2] = f2tf32(ra[i].z); p[3] = f2tf32(ra[i].w);
        }
        #pragma unroll
        for (int i = 0; i < 4; i++) {
            uint32_t* p = reinterpret_cast<uint32_t*>(s0 + A_FLOATS + bsm_off[i]);
            p[0] = f2tf32(rb[i].x); p[1] = f2tf32(rb[i].y);
            p[2] = f2tf32(rb[i].z); p[3] = f2tf32(rb[i].w);
        }
    }
    __syncthreads();

    for (int s = 0; s < NSTAGE; s++) {
        const int buf = s & 1;
        // issue next stage's global loads (latency hidden under MMA)
        if (s + 1 < NSTAGE) {
            const size_t ko = (size_t)(s + 1) * KC;
            #pragma unroll
            for (int i = 0; i < 8; i++)
                ra[i] = *reinterpret_cast<const float4*>(aptr[i] + ko);
            #pragma unroll
            for (int i = 0; i < 4; i++)
                rb[i] = *reinterpret_cast<const float4*>(bptr[i] + ko);
        }
        // ---- MMA over current buffer
        const uint32_t* sa = reinterpret_cast<const uint32_t*>(sm + buf * BUF_FLOATS);
        const uint32_t* sb = sa + A_FLOATS;
        #pragma unroll
        for (int kk = 0; kk < 8; kk++) {
            const int k0 = kk * 8 + (lane & 3);
            uint32_t af[2][4], bf[4][2];
            #pragma unroll
            for (int mtl = 0; mtl < 2; mtl++) {
                const int r = wm + mtl * 16 + (lane >> 2);
                af[mtl][0] = sa[r * ASTRIDE + k0];
                af[mtl][1] = sa[(r + 8) * ASTRIDE + k0];
                af[mtl][2] = sa[r * ASTRIDE + k0 + 4];
                af[mtl][3] = sa[(r + 8) * ASTRIDE + k0 + 4];
            }
            #pragma unroll
            for (int ntl = 0; ntl < 4; ntl++) {
                const int rn = wn + ntl * 8 + (lane >> 2);
                bf[ntl][0] = sb[rn * BSTRIDE + k0];
                bf[ntl][1] = sb[rn * BSTRIDE + k0 + 4];
            }
            #pragma unroll
            for (int mtl = 0; mtl < 2; mtl++)
                #pragma unroll
                for (int ntl = 0; ntl < 4; ntl++)
                    mma8(acc[mtl][ntl][0], acc[mtl][ntl][1],
                         acc[mtl][ntl][2], acc[mtl][ntl][3],
                         af[mtl][0], af[mtl][1], af[mtl][2], af[mtl][3],
                         bf[ntl][0], bf[ntl][1]);
        }
        // ---- store next stage into the other buffer (drained at bar of s-1)
        if (s + 1 < NSTAGE) {
            float* sn = sm + (buf ^ 1) * BUF_FLOATS;
            #pragma unroll
            for (int i = 0; i < 8; i++) {
                uint32_t* p = reinterpret_cast<uint32_t*>(sn + asm_off[i]);
                p[0] = f2tf32(ra[i].x); p[1] = f2tf32(ra[i].y);
                p[2] = f2tf32(ra[i].z); p[3] = f2tf32(ra[i].w);
            }
            #pragma unroll
            for (int i = 0; i < 4; i++) {
                uint32_t* p = reinterpret_cast<uint32_t*>(sn + A_FLOATS + bsm_off[i]);
                p[0] = f2tf32(rb[i].x); p[1] = f2tf32(rb[i].y);
                p[2] = f2tf32(rb[i].z); p[3] = f2tf32(rb[i].w);
            }
        }
        __syncthreads();
    }

    // ---- epilogue: bias + crelu, write g_comb[m][persp*256 + n]
    #pragma unroll
    for (int mtl = 0; mtl < 2; mtl++) {
        const int r = m0 + wm + mtl * 16 + (lane >> 2);
        #pragma unroll
        for (int ntl = 0; ntl < 4; ntl++) {
            const int nl = n0 + wn + ntl * 8 + (lane & 3) * 2;  // 0..255
            const float bb0 = bias[nl], bb1 = bias[nl + 1];
            const int fc = persp * 256 + nl;
            float2 v0, v1;
            v0.x = crelu(acc[mtl][ntl][0] + bb0);
            v0.y = crelu(acc[mtl][ntl][1] + bb1);
            v1.x = crelu(acc[mtl][ntl][2] + bb0);
            v1.y = crelu(acc[mtl][ntl][3] + bb1);
            *reinterpret_cast<float2*>(&g_comb[(size_t)r * 512 + fc])       = v0;
            *reinterpret_cast<float2*>(&g_comb[(size_t)(r + 8) * 512 + fc]) = v1;
        }
    }
}

// ================= Kernel 2: tail 512->32->32->1, one warp per batch row ========
__global__ void __launch_bounds__(256)
tail_kernel(const float* __restrict__ W2, const float* __restrict__ b2,
            const float* __restrict__ W3, const float* __restrict__ b3,
            const float* __restrict__ Wo, const float* __restrict__ bo,
            float* __restrict__ out)
{
    __shared__ float h1s[8][32];
    const int warp = threadIdx.x >> 5, lane = threadIdx.x & 31;
    const int row = blockIdx.x * 8 + warp;
    float c[16];
    #pragma unroll
    for (int t = 0; t < 16; t++) c[t] = g_comb[(size_t)row * 512 + t * 32 + lane];
    #pragma unroll 4
    for (int j = 0; j < 32; j++) {
        float a = 0.f;
        #pragma unroll
        for (int t = 0; t < 16; t++) a += W2[j * 512 + t * 32 + lane] * c[t];
        #pragma unroll
        for (int o = 16; o; o >>= 1) a += __shfl_xor_sync(0xFFFFFFFFu, a, o);
        if (lane == 0) h1s[warp][j] = crelu(a + b2[j]);
    }
    __syncwarp();
    float h2 = b3[lane];
    #pragma unroll
    for (int k = 0; k < 32; k++) h2 += W3[lane * 32 + k] * h1s[warp][k];
    h2 = crelu(h2);
    float v = h2 * Wo[lane];
    #pragma unroll
    for (int o = 16; o; o >>= 1) v += __shfl_xor_sync(0xFFFFFFFFu, v, o);
    if (lane == 0) out[row] = crelu(v + bo[0]);
}

extern "C" void kernel_launch(void* const* d_in, const int* in_sizes, int n_in,
                              void* d_out, int out_size)
{
    const float* xp  = (const float*)d_in[0];
    const float* xo  = (const float*)d_in[1];
    const float* W1p = (const float*)d_in[2];
    const float* b1p = (const float*)d_in[3];
    const float* W1o = (const float*)d_in[4];
    const float* b1o = (const float*)d_in[5];
    const float* W2  = (const float*)d_in[6];
    const float* b2  = (const float*)d_in[7];
    const float* W3  = (const float*)d_in[8];
    const float* b3  = (const float*)d_in[9];
    const float* Wo  = (const float*)d_in[10];
    const float* bo  = (const float*)d_in[11];

    static bool attr_set = false;
    if (!attr_set) {
        cudaFuncSetAttribute(ft_kernel, cudaFuncAttributeMaxDynamicSharedMemorySize,
                             SMEM_BYTES);
        attr_set = true;
    }
    ft_kernel<<<128, 256, SMEM_BYTES>>>(xp, xo, W1p, W1o, b1p, b1o);
    tail_kernel<<<256, 256>>>(W2, b2, W3, b3, Wo, bo, (float*)d_out);
}

// round 5
// speedup vs baseline: 1.9888x; 1.9888x over previous
#include <cuda_runtime.h>
#include <cuda_fp16.h>
#include <cstdint>

#define BATCH   2048
#define INSZ    40960
#define SPLITK  2
#define KLEN    (INSZ / SPLITK)    // 20480
#define KC      64
#define NSTAGE  (KLEN / KC)        // 320
#define ASTRW   36                 // smem row stride in 32-bit words (64 fp16 + 8 pad)
#define A_WORDS (128 * ASTRW)      // 4608
#define B_WORDS (128 * ASTRW)      // 4608
#define BUF_WORDS (A_WORDS + B_WORDS)          // 9216
#define SMEM_BYTES (2 * BUF_WORDS * 4)         // 73728

__device__ float g_partial[(size_t)BATCH * SPLITK * 512];  // [m][split][512]

__device__ __forceinline__ float crelu(float x) { return fminf(fmaxf(x, 0.f), 1.f); }

__device__ __forceinline__ uint32_t f2h2(float a, float b) {
    __half2 h = __floats2half2_rn(a, b);
    return *reinterpret_cast<uint32_t*>(&h);
}

__device__ __forceinline__ void mma16(float& c0, float& c1, float& c2, float& c3,
                                      uint32_t a0, uint32_t a1, uint32_t a2, uint32_t a3,
                                      uint32_t b0, uint32_t b1) {
    asm volatile(
        "mma.sync.aligned.m16n8k16.row.col.f32.f16.f16.f32 "
        "{%0,%1,%2,%3}, {%4,%5,%6,%7}, {%8,%9}, {%0,%1,%2,%3};"
        : "+f"(c0), "+f"(c1), "+f"(c2), "+f"(c3)
        : "r"(a0), "r"(a1), "r"(a2), "r"(a3), "r"(b0), "r"(b1));
}

// ========== Kernel 1: feature transformer GEMM, fp16 mma.sync, split-K=2 ==========
// grid = 128: ks = bid&1, nt = (bid>>1)&1, mt = (bid>>2)&15, persp = bid>>6
__global__ void __launch_bounds__(256, 1)
ft_kernel(const float* __restrict__ xp, const float* __restrict__ xo,
          const float* __restrict__ wp, const float* __restrict__ wo)
{
    extern __shared__ uint32_t sm[];
    const int tid = threadIdx.x, lane = tid & 31, wid = tid >> 5;
    const int bid = blockIdx.x;
    const int ks = bid & 1, nt = (bid >> 1) & 1, mt = (bid >> 2) & 15, persp = bid >> 6;
    const float* __restrict__ X = persp ? xo : xp;
    const float* __restrict__ W = persp ? wo : wp;
    const int m0 = mt * 128, n0 = nt * 128;
    const size_t kbase = (size_t)ks * KLEN;

    // producer addressing: A and B each 128 rows x 16 float4 quads = 2048 f4, 8/thread
    const float* aptr[8]; const float* bptr[8];
    int asw[8], bsw[8];
    #pragma unroll
    for (int i = 0; i < 8; i++) {
        int f = tid + i * 256, r = f >> 4, q = f & 15;
        aptr[i] = X + (size_t)(m0 + r) * INSZ + kbase + q * 4;
        bptr[i] = W + (size_t)(n0 + r) * INSZ + kbase + q * 4;
        asw[i] = r * ASTRW + q * 2;
        bsw[i] = r * ASTRW + q * 2;
    }

    const int wm = (wid & 3) * 32;    // 4 warps over M=128 (warp tile 32 rows)
    const int wn = (wid >> 2) * 64;   // 2 warps over N=128 (warp tile 64 cols)

    float acc[2][8][4];
    #pragma unroll
    for (int i = 0; i < 2; i++)
        #pragma unroll
        for (int j = 0; j < 8; j++)
            #pragma unroll
            for (int k = 0; k < 4; k++) acc[i][j][k] = 0.f;

    float4 ra[8], rb[8];
    // prologue stage 0
    #pragma unroll
    for (int i = 0; i < 8; i++) ra[i] = *reinterpret_cast<const float4*>(aptr[i]);
    #pragma unroll
    for (int i = 0; i < 8; i++) rb[i] = *reinterpret_cast<const float4*>(bptr[i]);
    #pragma unroll
    for (int i = 0; i < 8; i++) {
        uint32_t u0 = f2h2(ra[i].x, ra[i].y), u1 = f2h2(ra[i].z, ra[i].w);
        asm volatile("st.shared.v2.b32 [%0], {%1,%2};" :: "r"((uint32_t)(4 * asw[i]) +
            (uint32_t)__cvta_generic_to_shared(sm)), "r"(u0), "r"(u1) : "memory");
        uint32_t v0 = f2h2(rb[i].x, rb[i].y), v1 = f2h2(rb[i].z, rb[i].w);
        asm volatile("st.shared.v2.b32 [%0], {%1,%2};" :: "r"((uint32_t)(4 * (A_WORDS + bsw[i])) +
            (uint32_t)__cvta_generic_to_shared(sm)), "r"(v0), "r"(v1) : "memory");
    }
    __syncthreads();

    for (int s = 0; s < NSTAGE; s++) {
        const int buf = s & 1;
        if (s + 1 < NSTAGE) {
            const size_t ko = (size_t)(s + 1) * KC;
            #pragma unroll
            for (int i = 0; i < 8; i++) ra[i] = *reinterpret_cast<const float4*>(aptr[i] + ko);
            #pragma unroll
            for (int i = 0; i < 8; i++) rb[i] = *reinterpret_cast<const float4*>(bptr[i] + ko);
        }
        const uint32_t* sa = sm + buf * BUF_WORDS;
        const uint32_t* sb = sa + A_WORDS;
        #pragma unroll
        for (int kk = 0; kk < 4; kk++) {        // 4 x k16 chunks
            const int kw = kk * 8 + (lane & 3);
            uint32_t af[2][4], bf[8][2];
            #pragma unroll
            for (int mtl = 0; mtl < 2; mtl++) {
                const int r = wm + mtl * 16 + (lane >> 2);
                af[mtl][0] = sa[r * ASTRW + kw];
                af[mtl][1] = sa[(r + 8) * ASTRW + kw];
                af[mtl][2] = sa[r * ASTRW + kw + 4];
                af[mtl][3] = sa[(r + 8) * ASTRW + kw + 4];
            }
            #pragma unroll
            for (int ntl = 0; ntl < 8; ntl++) {
                const int rn = wn + ntl * 8 + (lane >> 2);
                bf[ntl][0] = sb[rn * ASTRW + kw];
                bf[ntl][1] = sb[rn * ASTRW + kw + 4];
            }
            #pragma unroll
            for (int mtl = 0; mtl < 2; mtl++)
                #pragma unroll
                for (int ntl = 0; ntl < 8; ntl++)
                    mma16(acc[mtl][ntl][0], acc[mtl][ntl][1],
                          acc[mtl][ntl][2], acc[mtl][ntl][3],
                          af[mtl][0], af[mtl][1], af[mtl][2], af[mtl][3],
                          bf[ntl][0], bf[ntl][1]);
        }
        if (s + 1 < NSTAGE) {
            uint32_t* sn = sm + (buf ^ 1) * BUF_WORDS;
            #pragma unroll
            for (int i = 0; i < 8; i++) {
                uint32_t u0 = f2h2(ra[i].x, ra[i].y), u1 = f2h2(ra[i].z, ra[i].w);
                asm volatile("st.shared.v2.b32 [%0], {%1,%2};" :: "r"((uint32_t)(4 * asw[i]) +
                    (uint32_t)__cvta_generic_to_shared(sn)), "r"(u0), "r"(u1) : "memory");
                uint32_t v0 = f2h2(rb[i].x, rb[i].y), v1 = f2h2(rb[i].z, rb[i].w);
                asm volatile("st.shared.v2.b32 [%0], {%1,%2};" :: "r"((uint32_t)(4 * (A_WORDS + bsw[i])) +
                    (uint32_t)__cvta_generic_to_shared(sn)), "r"(v0), "r"(v1) : "memory");
            }
        }
        __syncthreads();
    }

    // epilogue: write fp32 split-K partials, no bias (added in reduce_tail)
    #pragma unroll
    for (int mtl = 0; mtl < 2; mtl++) {
        const int m = m0 + wm + mtl * 16 + (lane >> 2);
        #pragma unroll
        for (int ntl = 0; ntl < 8; ntl++) {
            const int col = n0 + wn + ntl * 8 + (lane & 3) * 2;
            const int f = persp * 256 + col;
            float2 v0 = make_float2(acc[mtl][ntl][0], acc[mtl][ntl][1]);
            float2 v1 = make_float2(acc[mtl][ntl][2], acc[mtl][ntl][3]);
            *reinterpret_cast<float2*>(&g_partial[((size_t)m * SPLITK + ks) * 512 + f]) = v0;
            *reinterpret_cast<float2*>(&g_partial[((size_t)(m + 8) * SPLITK + ks) * 512 + f]) = v1;
        }
    }
}

// ========== Kernel 2: fused split-K reduce + bias + crelu + tail MLP ==========
// grid = 128 blocks x 256 threads; block handles 16 batch rows.
__global__ void __launch_bounds__(256)
reduce_tail(const float* __restrict__ b1p, const float* __restrict__ b1o,
            const float* __restrict__ W2, const float* __restrict__ b2,
            const float* __restrict__ W3, const float* __restrict__ b3,
            const float* __restrict__ Wo, const float* __restrict__ bo,
            float* __restrict__ out)
{
    __shared__ float comb[16][516];
    __shared__ float h1s[8][32];
    const int tid = threadIdx.x, lane = tid & 31, wid = tid >> 5;
    const int R0 = blockIdx.x * 16;

    // phase 1: reduce splits + bias + crelu into smem
    #pragma unroll
    for (int it = 0; it < 8; it++) {
        const int idx = it * 256 + tid;       // f4 index over 16 rows x 128 f4
        const int row = idx >> 7, fq = idx & 127;
        const size_t m = R0 + row;
        float4 p0 = *reinterpret_cast<const float4*>(&g_partial[(m * SPLITK + 0) * 512 + fq * 4]);
        float4 p1 = *reinterpret_cast<const float4*>(&g_partial[(m * SPLITK + 1) * 512 + fq * 4]);
        const int f = fq * 4;
        float4 bv = (f < 256) ? *reinterpret_cast<const float4*>(&b1p[f])
                              : *reinterpret_cast<const float4*>(&b1o[f - 256]);
        comb[row][f + 0] = crelu(p0.x + p1.x + bv.x);
        comb[row][f + 1] = crelu(p0.y + p1.y + bv.y);
        comb[row][f + 2] = crelu(p0.z + p1.z + bv.z);
        comb[row][f + 3] = crelu(p0.w + p1.w + bv.w);
    }
    __syncthreads();

    // phase 2: per-warp tail, 2 rows each
    for (int rr = 0; rr < 2; rr++) {
        const int row = wid * 2 + rr;         // 0..15
        float c[16];
        #pragma unroll
        for (int t = 0; t < 16; t++) c[t] = comb[row][t * 32 + lane];
        #pragma unroll 4
        for (int j = 0; j < 32; j++) {
            float a = 0.f;
            #pragma unroll
            for (int t = 0; t < 16; t++) a += W2[j * 512 + t * 32 + lane] * c[t];
            #pragma unroll
            for (int o = 16; o; o >>= 1) a += __shfl_xor_sync(0xFFFFFFFFu, a, o);
            if (lane == 0) h1s[wid][j] = crelu(a + b2[j]);
        }
        __syncwarp();
        float h2 = b3[lane];
        #pragma unroll
        for (int k = 0; k < 32; k++) h2 += W3[lane * 32 + k] * h1s[wid][k];
        h2 = crelu(h2);
        float v = h2 * Wo[lane];
        #pragma unroll
        for (int o = 16; o; o >>= 1) v += __shfl_xor_sync(0xFFFFFFFFu, v, o);
        if (lane == 0) out[R0 + row] = crelu(v + bo[0]);
        __syncwarp();
    }
}

extern "C" void kernel_launch(void* const* d_in, const int* in_sizes, int n_in,
                              void* d_out, int out_size)
{
    const float* xp  = (const float*)d_in[0];
    const float* xo  = (const float*)d_in[1];
    const float* W1p = (const float*)d_in[2];
    const float* b1p = (const float*)d_in[3];
    const float* W1o = (const float*)d_in[4];
    const float* b1o = (const float*)d_in[5];
    const float* W2  = (const float*)d_in[6];
    const float* b2  = (const float*)d_in[7];
    const float* W3  = (const float*)d_in[8];
    const float* b3  = (const float*)d_in[9];
    const float* Wo  = (const float*)d_in[10];
    const float* bo  = (const float*)d_in[11];

    static bool attr_set = false;
    if (!attr_set) {
        cudaFuncSetAttribute(ft_kernel, cudaFuncAttributeMaxDynamicSharedMemorySize,
                             SMEM_BYTES);
        attr_set = true;
    }
    ft_kernel<<<128, 256, SMEM_BYTES>>>(xp, xo, W1p, W1o);
    reduce_tail<<<128, 256>>>(b1p, b1o, W2, b2, W3, b3, Wo, bo, (float*)d_out);
}

// round 6
// speedup vs baseline: 2.3560x; 1.1846x over previous
#include <cuda_runtime.h>
#include <cuda_fp16.h>
#include <cstdint>

#define BATCH   2048
#define INSZ    40960
#define SPLITK  2
#define KLEN    (INSZ / SPLITK)    // 20480
#define KC      64
#define NSTAGE  (KLEN / KC)        // 320
#define ASTRW   36                 // smem row stride in 32-bit words (64 fp16 + pad)
#define A_WORDS (128 * ASTRW)
#define B_WORDS (128 * ASTRW)
#define BUF_WORDS (A_WORDS + B_WORDS)
#define SMEM_BYTES (2 * BUF_WORDS * 4)        // 73728

// tail smem carve (floats)
#define TW2_STRIDE 516
#define TW2_FLOATS (32 * TW2_STRIDE)          // 16512
#define TCOMB_STRIDE 516
#define TCOMB_FLOATS (8 * TCOMB_STRIDE)       // 4128
#define TH1_FLOATS (8 * 32)
#define TAIL_SMEM_BYTES ((TW2_FLOATS + TCOMB_FLOATS + TH1_FLOATS) * 4)  // ~83.6KB

__device__ float g_partial[(size_t)BATCH * SPLITK * 512];  // [m][split][512]

__device__ __forceinline__ float crelu(float x) { return fminf(fmaxf(x, 0.f), 1.f); }

__device__ __forceinline__ uint32_t f2h2(float a, float b) {
    __half2 h = __floats2half2_rn(a, b);
    return *reinterpret_cast<uint32_t*>(&h);
}

__device__ __forceinline__ void mma16(float& c0, float& c1, float& c2, float& c3,
                                      uint32_t a0, uint32_t a1, uint32_t a2, uint32_t a3,
                                      uint32_t b0, uint32_t b1) {
    asm volatile(
        "mma.sync.aligned.m16n8k16.row.col.f32.f16.f16.f32 "
        "{%0,%1,%2,%3}, {%4,%5,%6,%7}, {%8,%9}, {%0,%1,%2,%3};"
        : "+f"(c0), "+f"(c1), "+f"(c2), "+f"(c3)
        : "r"(a0), "r"(a1), "r"(a2), "r"(a3), "r"(b0), "r"(b1));
}

// ========== Kernel 1: feature transformer GEMM, fp16 mma.sync, split-K=2 ==========
__global__ void __launch_bounds__(256, 1)
ft_kernel(const float* __restrict__ xp, const float* __restrict__ xo,
          const float* __restrict__ wp, const float* __restrict__ wo)
{
    extern __shared__ uint32_t sm[];
    const int tid = threadIdx.x, lane = tid & 31, wid = tid >> 5;
    const int bid = blockIdx.x;
    const int ks = bid & 1, nt = (bid >> 1) & 1, mt = (bid >> 2) & 15, persp = bid >> 6;
    const float* __restrict__ X = persp ? xo : xp;
    const float* __restrict__ W = persp ? wo : wp;
    const int m0 = mt * 128, n0 = nt * 128;
    const size_t kbase = (size_t)ks * KLEN;

    const float* aptr[8]; const float* bptr[8];
    uint32_t asw[8], bsw[8];
    const uint32_t smb = (uint32_t)__cvta_generic_to_shared(sm);
    #pragma unroll
    for (int i = 0; i < 8; i++) {
        int f = tid + i * 256, r = f >> 4, q = f & 15;
        aptr[i] = X + (size_t)(m0 + r) * INSZ + kbase + q * 4;
        bptr[i] = W + (size_t)(n0 + r) * INSZ + kbase + q * 4;
        asw[i] = smb + 4u * (r * ASTRW + q * 2);
        bsw[i] = smb + 4u * (A_WORDS + r * ASTRW + q * 2);
    }

    const int wm = (wid & 3) * 32;
    const int wn = (wid >> 2) * 64;

    float acc[2][8][4];
    #pragma unroll
    for (int i = 0; i < 2; i++)
        #pragma unroll
        for (int j = 0; j < 8; j++)
            #pragma unroll
            for (int k = 0; k < 4; k++) acc[i][j][k] = 0.f;

    float4 ra[8], rb[8];
    // prologue: stage 0 -> buf0, publish, then preload stage 1 into regs
    #pragma unroll
    for (int i = 0; i < 8; i++) ra[i] = *reinterpret_cast<const float4*>(aptr[i]);
    #pragma unroll
    for (int i = 0; i < 8; i++) rb[i] = *reinterpret_cast<const float4*>(bptr[i]);
    #pragma unroll
    for (int i = 0; i < 8; i++) {
        uint32_t u0 = f2h2(ra[i].x, ra[i].y), u1 = f2h2(ra[i].z, ra[i].w);
        asm volatile("st.shared.v2.b32 [%0], {%1,%2};" :: "r"(asw[i]), "r"(u0), "r"(u1) : "memory");
        uint32_t v0 = f2h2(rb[i].x, rb[i].y), v1 = f2h2(rb[i].z, rb[i].w);
        asm volatile("st.shared.v2.b32 [%0], {%1,%2};" :: "r"(bsw[i]), "r"(v0), "r"(v1) : "memory");
    }
    __syncthreads();
    #pragma unroll
    for (int i = 0; i < 8; i++) ra[i] = *reinterpret_cast<const float4*>(aptr[i] + KC);
    #pragma unroll
    for (int i = 0; i < 8; i++) rb[i] = *reinterpret_cast<const float4*>(bptr[i] + KC);

    for (int s = 0; s < NSTAGE; s++) {
        const int buf = s & 1;
        // 1) STS stage s+1 (regs loaded one stage ago) into the other buffer
        if (s + 1 < NSTAGE) {
            const uint32_t boff = (uint32_t)((buf ^ 1) * BUF_WORDS * 4);
            #pragma unroll
            for (int i = 0; i < 8; i++) {
                uint32_t u0 = f2h2(ra[i].x, ra[i].y), u1 = f2h2(ra[i].z, ra[i].w);
                asm volatile("st.shared.v2.b32 [%0], {%1,%2};" :: "r"(asw[i] + boff), "r"(u0), "r"(u1) : "memory");
                uint32_t v0 = f2h2(rb[i].x, rb[i].y), v1 = f2h2(rb[i].z, rb[i].w);
                asm volatile("st.shared.v2.b32 [%0], {%1,%2};" :: "r"(bsw[i] + boff), "r"(v0), "r"(v1) : "memory");
            }
        }
        // 2) issue LDG for stage s+2 (latency hidden under MMA of s and s+1)
        if (s + 2 < NSTAGE) {
            const size_t ko = (size_t)(s + 2) * KC;
            #pragma unroll
            for (int i = 0; i < 8; i++) ra[i] = *reinterpret_cast<const float4*>(aptr[i] + ko);
            #pragma unroll
            for (int i = 0; i < 8; i++) rb[i] = *reinterpret_cast<const float4*>(bptr[i] + ko);
        }
        // 3) MMA over current buffer
        const uint32_t* sa = sm + buf * BUF_WORDS;
        const uint32_t* sb = sa + A_WORDS;
        #pragma unroll
        for (int kk = 0; kk < 4; kk++) {
            const int kw = kk * 8 + (lane & 3);
            uint32_t af[2][4], bf[8][2];
            #pragma unroll
            for (int mtl = 0; mtl < 2; mtl++) {
                const int r = wm + mtl * 16 + (lane >> 2);
                af[mtl][0] = sa[r * ASTRW + kw];
                af[mtl][1] = sa[(r + 8) * ASTRW + kw];
                af[mtl][2] = sa[r * ASTRW + kw + 4];
                af[mtl][3] = sa[(r + 8) * ASTRW + kw + 4];
            }
            #pragma unroll
            for (int ntl = 0; ntl < 8; ntl++) {
                const int rn = wn + ntl * 8 + (lane >> 2);
                bf[ntl][0] = sb[rn * ASTRW + kw];
                bf[ntl][1] = sb[rn * ASTRW + kw + 4];
            }
            #pragma unroll
            for (int mtl = 0; mtl < 2; mtl++)
                #pragma unroll
                for (int ntl = 0; ntl < 8; ntl++)
                    mma16(acc[mtl][ntl][0], acc[mtl][ntl][1],
                          acc[mtl][ntl][2], acc[mtl][ntl][3],
                          af[mtl][0], af[mtl][1], af[mtl][2], af[mtl][3],
                          bf[ntl][0], bf[ntl][1]);
        }
        __syncthreads();
    }

    // epilogue: fp32 split-K partials
    #pragma unroll
    for (int mtl = 0; mtl < 2; mtl++) {
        const int m = m0 + wm + mtl * 16 + (lane >> 2);
        #pragma unroll
        for (int ntl = 0; ntl < 8; ntl++) {
            const int col = n0 + wn + ntl * 8 + (lane & 3) * 2;
            const int f = persp * 256 + col;
            float2 v0 = make_float2(acc[mtl][ntl][0], acc[mtl][ntl][1]);
            float2 v1 = make_float2(acc[mtl][ntl][2], acc[mtl][ntl][3]);
            *reinterpret_cast<float2*>(&g_partial[((size_t)m * SPLITK + ks) * 512 + f]) = v0;
            *reinterpret_cast<float2*>(&g_partial[((size_t)(m + 8) * SPLITK + ks) * 512 + f]) = v1;
        }
    }
}

// ========== Kernel 2: fused reduce + bias + crelu + tail, lane-parallel layer-2 ====
// grid = 256 blocks x 256 threads; block handles 8 batch rows, warp = one row, lane = j.
__global__ void __launch_bounds__(256)
reduce_tail(const float* __restrict__ b1p, const float* __restrict__ b1o,
            const float* __restrict__ W2, const float* __restrict__ b2,
            const float* __restrict__ W3, const float* __restrict__ b3,
            const float* __restrict__ Wo, const float* __restrict__ bo,
            float* __restrict__ out)
{
    extern __shared__ float ts[];
    float* W2s  = ts;                       // [32][516]
    float* comb = ts + TW2_FLOATS;          // [8][516]
    float* h1s  = comb + TCOMB_FLOATS;      // [8][32]
    const int tid = threadIdx.x, lane = tid & 31, wid = tid >> 5;
    const int R0 = blockIdx.x * 8;

    // phase 1a: reduce splits + bias + crelu into comb
    #pragma unroll
    for (int it = 0; it < 4; it++) {
        const int idx = it * 256 + tid;            // 8 rows x 128 f4
        const int row = idx >> 7, fq = idx & 127;
        const size_t m = R0 + row;
        float4 p0 = *reinterpret_cast<const float4*>(&g_partial[(m * SPLITK + 0) * 512 + fq * 4]);
        float4 p1 = *reinterpret_cast<const float4*>(&g_partial[(m * SPLITK + 1) * 512 + fq * 4]);
        const int f = fq * 4;
        float4 bv = (f < 256) ? *reinterpret_cast<const float4*>(&b1p[f])
                              : *reinterpret_cast<const float4*>(&b1o[f - 256]);
        float* c = comb + row * TCOMB_STRIDE + f;
        c[0] = crelu(p0.x + p1.x + bv.x);
        c[1] = crelu(p0.y + p1.y + bv.y);
        c[2] = crelu(p0.z + p1.z + bv.z);
        c[3] = crelu(p0.w + p1.w + bv.w);
    }
    // phase 1b: stage W2 into smem (row j at stride 516)
    #pragma unroll
    for (int it = 0; it < 16; it++) {
        const int idx = it * 256 + tid;            // 4096 f4 = 32x512 floats
        const int j = idx >> 7, k = (idx & 127) * 4;
        float4 w = *reinterpret_cast<const float4*>(&W2[j * 512 + k]);
        *reinterpret_cast<float4*>(&W2s[j * TW2_STRIDE + k]) = w;
    }
    __syncthreads();

    // phase 2: warp = row (wid), lane = output j. No shfl in layer 2.
    {
        const int row = wid;
        const float* w2r = W2s + lane * TW2_STRIDE;
        const float* cr  = comb + row * TCOMB_STRIDE;
        float a = b2[lane];
        #pragma unroll 8
        for (int k4 = 0; k4 < 128; k4++) {
            float4 w = *reinterpret_cast<const float4*>(&w2r[k4 * 4]);
            float4 c = *reinterpret_cast<const float4*>(&cr[k4 * 4]);
            a += w.x * c.x + w.y * c.y + w.z * c.z + w.w * c.w;
        }
        h1s[row * 32 + lane] = crelu(a);
        __syncwarp();
        float h2 = b3[lane];
        #pragma unroll
        for (int k = 0; k < 32; k++) h2 += W3[lane * 32 + k] * h1s[row * 32 + k];
        h2 = crelu(h2);
        float v = h2 * Wo[lane];
        #pragma unroll
        for (int o = 16; o; o >>= 1) v += __shfl_xor_sync(0xFFFFFFFFu, v, o);
        if (lane == 0) out[R0 + row] = crelu(v + bo[0]);
    }
}

extern "C" void kernel_launch(void* const* d_in, const int* in_sizes, int n_in,
                              void* d_out, int out_size)
{
    const float* xp  = (const float*)d_in[0];
    const float* xo  = (const float*)d_in[1];
    const float* W1p = (const float*)d_in[2];
    const float* b1p = (const float*)d_in[3];
    const float* W1o = (const float*)d_in[4];
    const float* b1o = (const float*)d_in[5];
    const float* W2  = (const float*)d_in[6];
    const float* b2  = (const float*)d_in[7];
    const float* W3  = (const float*)d_in[8];
    const float* b3  = (const float*)d_in[9];
    const float* Wo  = (const float*)d_in[10];
    const float* bo  = (const float*)d_in[11];

    static bool attr_set = false;
    if (!attr_set) {
        cudaFuncSetAttribute(ft_kernel, cudaFuncAttributeMaxDynamicSharedMemorySize,
                             SMEM_BYTES);
        cudaFuncSetAttribute(reduce_tail, cudaFuncAttributeMaxDynamicSharedMemorySize,
                             TAIL_SMEM_BYTES);
        attr_set = true;
    }
    ft_kernel<<<128, 256, SMEM_BYTES>>>(xp, xo, W1p, W1o);
    reduce_tail<<<256, 256, TAIL_SMEM_BYTES>>>(b1p, b1o, W2, b2, W3, b3, Wo, bo,
                                               (float*)d_out);
}

// round 7
// speedup vs baseline: 2.8541x; 1.2114x over previous
#include <cuda_runtime.h>
#include <cuda_fp16.h>
#include <cstdint>

#define BATCH   2048
#define INSZ    40960
#define KC      64
#define KSTPT   640                 // k-stages per tile (40960/64)
#define NTILE   64                  // 2 persp x 16 mt x 2 nt
#define TOTS    (NTILE * KSTPT)     // 40960 stage-units
#define ASTRW   36                  // smem row stride in words (64 fp16 + pad)
#define A_WORDS (128 * ASTRW)
#define BUF_WORDS (2 * A_WORDS)
#define SMEM_BYTES (2 * BUF_WORDS * 4)   // 73728

// tail smem carve (floats)
#define TW2_STRIDE 516
#define TW2_FLOATS (32 * TW2_STRIDE)
#define TCOMB_STRIDE 516
#define TCOMB_FLOATS (8 * TCOMB_STRIDE)
#define TH1_FLOATS (8 * 32)
#define TAIL_SMEM_BYTES ((TW2_FLOATS + TCOMB_FLOATS + TH1_FLOATS) * 4)

// partials: [tile][slot(4)][m_local(128)][n_local(128)] = 16 MB
__device__ float g_partial[(size_t)NTILE * 4 * 128 * 128];

__device__ __forceinline__ float crelu(float x) { return fminf(fmaxf(x, 0.f), 1.f); }

__device__ __forceinline__ uint32_t f2h2(float a, float b) {
    __half2 h = __floats2half2_rn(a, b);
    return *reinterpret_cast<uint32_t*>(&h);
}

__device__ __forceinline__ void mma16(float& c0, float& c1, float& c2, float& c3,
                                      uint32_t a0, uint32_t a1, uint32_t a2, uint32_t a3,
                                      uint32_t b0, uint32_t b1) {
    asm volatile(
        "mma.sync.aligned.m16n8k16.row.col.f32.f16.f16.f32 "
        "{%0,%1,%2,%3}, {%4,%5,%6,%7}, {%8,%9}, {%0,%1,%2,%3};"
        : "+f"(c0), "+f"(c1), "+f"(c2), "+f"(c3)
        : "r"(a0), "r"(a1), "r"(a2), "r"(a3), "r"(b0), "r"(b1));
}

__global__ void zero_kernel() {
    const size_t idx = (size_t)blockIdx.x * 256 + threadIdx.x;
    reinterpret_cast<float4*>(g_partial)[idx] = make_float4(0.f, 0.f, 0.f, 0.f);
}

__global__ void dummy_kernel() {}

// ========== Kernel 1: feature transformer GEMM, even stage-partition over all SMs ====
__global__ void __launch_bounds__(256, 1)
ft_kernel(const float* __restrict__ xp, const float* __restrict__ xo,
          const float* __restrict__ wp, const float* __restrict__ wo)
{
    extern __shared__ uint32_t sm[];
    const int tid = threadIdx.x, lane = tid & 31, wid = tid >> 5;
    const int G = gridDim.x, ib = blockIdx.x;
    int S = (int)((long)ib * TOTS / G);
    const int S_hi = (int)((long)(ib + 1) * TOTS / G);
    const uint32_t smb = (uint32_t)__cvta_generic_to_shared(sm);
    const int wm = (wid & 3) * 32;
    const int wn = (wid >> 2) * 64;

    while (S < S_hi) {
        const int t    = S / KSTPT;
        const int send = min(S_hi, (t + 1) * KSTPT);
        const int ks0  = S - t * KSTPT;
        const int len  = send - S;
        const int persp = t >> 5, mt = (t >> 1) & 15, nt = t & 1;
        const float* __restrict__ X = persp ? xo : xp;
        const float* __restrict__ W = persp ? wo : wp;
        const int m0 = mt * 128, n0 = nt * 128;
        const size_t kbase = (size_t)ks0 * KC;

        const float* aptr[8]; const float* bptr[8];
        uint32_t asw[8], bsw[8];
        #pragma unroll
        for (int j = 0; j < 8; j++) {
            int f = tid + j * 256, r = f >> 4, q = f & 15;
            aptr[j] = X + (size_t)(m0 + r) * INSZ + kbase + q * 4;
            bptr[j] = W + (size_t)(n0 + r) * INSZ + kbase + q * 4;
            asw[j] = smb + 4u * (r * ASTRW + q * 2);
            bsw[j] = smb + 4u * (A_WORDS + r * ASTRW + q * 2);
        }

        float acc[2][8][4];
        #pragma unroll
        for (int a = 0; a < 2; a++)
            #pragma unroll
            for (int b = 0; b < 8; b++)
                #pragma unroll
                for (int c = 0; c < 4; c++) acc[a][b][c] = 0.f;

        float4 ra[8], rb[8];
        // prologue: stage 0 -> buf0
        #pragma unroll
        for (int j = 0; j < 8; j++) ra[j] = *reinterpret_cast<const float4*>(aptr[j]);
        #pragma unroll
        for (int j = 0; j < 8; j++) rb[j] = *reinterpret_cast<const float4*>(bptr[j]);
        #pragma unroll
        for (int j = 0; j < 8; j++) {
            uint32_t u0 = f2h2(ra[j].x, ra[j].y), u1 = f2h2(ra[j].z, ra[j].w);
            asm volatile("st.shared.v2.b32 [%0], {%1,%2};" :: "r"(asw[j]), "r"(u0), "r"(u1) : "memory");
            uint32_t v0 = f2h2(rb[j].x, rb[j].y), v1 = f2h2(rb[j].z, rb[j].w);
            asm volatile("st.shared.v2.b32 [%0], {%1,%2};" :: "r"(bsw[j]), "r"(v0), "r"(v1) : "memory");
        }
        __syncthreads();
        if (len > 1) {
            #pragma unroll
            for (int j = 0; j < 8; j++) ra[j] = *reinterpret_cast<const float4*>(aptr[j] + KC);
            #pragma unroll
            for (int j = 0; j < 8; j++) rb[j] = *reinterpret_cast<const float4*>(bptr[j] + KC);
        }

        for (int s2 = 0; s2 < len; s2++) {
            const int buf = s2 & 1;
            if (s2 + 1 < len) {
                const uint32_t boff = (uint32_t)((buf ^ 1) * BUF_WORDS * 4);
                #pragma unroll
                for (int j = 0; j < 8; j++) {
                    uint32_t u0 = f2h2(ra[j].x, ra[j].y), u1 = f2h2(ra[j].z, ra[j].w);
                    asm volatile("st.shared.v2.b32 [%0], {%1,%2};" :: "r"(asw[j] + boff), "r"(u0), "r"(u1) : "memory");
                    uint32_t v0 = f2h2(rb[j].x, rb[j].y), v1 = f2h2(rb[j].z, rb[j].w);
                    asm volatile("st.shared.v2.b32 [%0], {%1,%2};" :: "r"(bsw[j] + boff), "r"(v0), "r"(v1) : "memory");
                }
            }
            if (s2 + 2 < len) {
                const size_t ko = (size_t)(s2 + 2) * KC;
                #pragma unroll
                for (int j = 0; j < 8; j++) ra[j] = *reinterpret_cast<const float4*>(aptr[j] + ko);
                #pragma unroll
                for (int j = 0; j < 8; j++) rb[j] = *reinterpret_cast<const float4*>(bptr[j] + ko);
            }
            const uint32_t* sa = sm + buf * BUF_WORDS;
            const uint32_t* sb = sa + A_WORDS;
            #pragma unroll
            for (int kk = 0; kk < 4; kk++) {
                const int kw = kk * 8 + (lane & 3);
                uint32_t af[2][4], bf[8][2];
                #pragma unroll
                for (int mtl = 0; mtl < 2; mtl++) {
                    const int r = wm + mtl * 16 + (lane >> 2);
                    af[mtl][0] = sa[r * ASTRW + kw];
                    af[mtl][1] = sa[(r + 8) * ASTRW + kw];
                    af[mtl][2] = sa[r * ASTRW + kw + 4];
                    af[mtl][3] = sa[(r + 8) * ASTRW + kw + 4];
                }
                #pragma unroll
                for (int ntl = 0; ntl < 8; ntl++) {
                    const int rn = wn + ntl * 8 + (lane >> 2);
                    bf[ntl][0] = sb[rn * ASTRW + kw];
                    bf[ntl][1] = sb[rn * ASTRW + kw + 4];
                }
                #pragma unroll
                for (int mtl = 0; mtl < 2; mtl++)
                    #pragma unroll
                    for (int ntl = 0; ntl < 8; ntl++)
                        mma16(acc[mtl][ntl][0], acc[mtl][ntl][1],
                              acc[mtl][ntl][2], acc[mtl][ntl][3],
                              af[mtl][0], af[mtl][1], af[mtl][2], af[mtl][3],
                              bf[ntl][0], bf[ntl][1]);
            }
            __syncthreads();
        }

        // epilogue: deterministic slot = ib - owner(first stage of tile t)
        const int owner0 = (int)(((long)(t * KSTPT + 1) * G + TOTS - 1) / TOTS) - 1;
        const int slot = ib - owner0;       // 0..3
        float* gp = g_partial + ((size_t)t * 4 + slot) * 16384;
        #pragma unroll
        for (int mtl = 0; mtl < 2; mtl++) {
            const int ml = wm + mtl * 16 + (lane >> 2);
            #pragma unroll
            for (int ntl = 0; ntl < 8; ntl++) {
                const int col = wn + ntl * 8 + (lane & 3) * 2;
                *reinterpret_cast<float2*>(&gp[(size_t)ml * 128 + col]) =
                    make_float2(acc[mtl][ntl][0], acc[mtl][ntl][1]);
                *reinterpret_cast<float2*>(&gp[(size_t)(ml + 8) * 128 + col]) =
                    make_float2(acc[mtl][ntl][2], acc[mtl][ntl][3]);
            }
        }
        S = send;
    }
}

// ========== Kernel 2: fused 4-slot reduce + bias + crelu + tail MLP ==========
__global__ void __launch_bounds__(256)
reduce_tail(const float* __restrict__ b1p, const float* __restrict__ b1o,
            const float* __restrict__ W2, const float* __restrict__ b2,
            const float* __restrict__ W3, const float* __restrict__ b3,
            const float* __restrict__ Wo, const float* __restrict__ bo,
            float* __restrict__ out)
{
    extern __shared__ float ts[];
    float* W2s  = ts;                       // [32][516]
    float* comb = ts + TW2_FLOATS;          // [8][516]
    float* h1s  = comb + TCOMB_FLOATS;      // [8][32]
    const int tid = threadIdx.x, lane = tid & 31, wid = tid >> 5;
    const int R0 = blockIdx.x * 8;

    #pragma unroll
    for (int it = 0; it < 4; it++) {
        const int idx = it * 256 + tid;            // 8 rows x 128 f4
        const int row = idx >> 7, fq = idx & 127;
        const int m = R0 + row;
        const int f = fq * 4;
        const int persp = f >> 8;
        const int ntl = (f >> 7) & 1;
        const int c = f & 127;
        const int t = persp * 32 + (m >> 7) * 2 + ntl;
        const float* gp = g_partial + (size_t)t * 4 * 16384 + (size_t)(m & 127) * 128 + c;
        float4 bv = (f < 256) ? *reinterpret_cast<const float4*>(&b1p[f])
                              : *reinterpret_cast<const float4*>(&b1o[f - 256]);
        float4 s = bv;
        #pragma unroll
        for (int sl = 0; sl < 4; sl++) {
            float4 v = *reinterpret_cast<const float4*>(gp + (size_t)sl * 16384);
            s.x += v.x; s.y += v.y; s.z += v.z; s.w += v.w;
        }
        float* cc = comb + row * TCOMB_STRIDE + f;
        cc[0] = crelu(s.x); cc[1] = crelu(s.y); cc[2] = crelu(s.z); cc[3] = crelu(s.w);
    }
    #pragma unroll
    for (int it = 0; it < 16; it++) {
        const int idx = it * 256 + tid;
        const int j = idx >> 7, k = (idx & 127) * 4;
        *reinterpret_cast<float4*>(&W2s[j * TW2_STRIDE + k]) =
            *reinterpret_cast<const float4*>(&W2[j * 512 + k]);
    }
    __syncthreads();

    {
        const int row = wid;
        const float* w2r = W2s + lane * TW2_STRIDE;
        const float* cr  = comb + row * TCOMB_STRIDE;
        float a = b2[lane];
        #pragma unroll 8
        for (int k4 = 0; k4 < 128; k4++) {
            float4 w = *reinterpret_cast<const float4*>(&w2r[k4 * 4]);
            float4 c = *reinterpret_cast<const float4*>(&cr[k4 * 4]);
            a += w.x * c.x + w.y * c.y + w.z * c.z + w.w * c.w;
        }
        h1s[row * 32 + lane] = crelu(a);
        __syncwarp();
        float h2 = b3[lane];
        #pragma unroll
        for (int k = 0; k < 32; k++) h2 += W3[lane * 32 + k] * h1s[row * 32 + k];
        h2 = crelu(h2);
        float v = h2 * Wo[lane];
        #pragma unroll
        for (int o = 16; o; o >>= 1) v += __shfl_xor_sync(0xFFFFFFFFu, v, o);
        if (lane == 0) out[R0 + row] = crelu(v + bo[0]);
    }
}

extern "C" void kernel_launch(void* const* d_in, const int* in_sizes, int n_in,
                              void* d_out, int out_size)
{
    const float* xp  = (const float*)d_in[0];
    const float* xo  = (const float*)d_in[1];
    const float* W1p = (const float*)d_in[2];
    const float* b1p = (const float*)d_in[3];
    const float* W1o = (const float*)d_in[4];
    const float* b1o = (const float*)d_in[5];
    const float* W2  = (const float*)d_in[6];
    const float* b2  = (const float*)d_in[7];
    const float* W3  = (const float*)d_in[8];
    const float* b3  = (const float*)d_in[9];
    const float* Wo  = (const float*)d_in[10];
    const float* bo  = (const float*)d_in[11];

    static int grid_ft = 0;
    if (grid_ft == 0) {
        int smc = 148;
        cudaDeviceGetAttribute(&smc, cudaDevAttrMultiProcessorCount, 0);
        if (smc > 160) smc = 160;     // slot bound (<=4 partials per tile) needs chunk>=256
        if (smc < 64)  smc = 64;
        grid_ft = smc;
        cudaFuncSetAttribute(ft_kernel, cudaFuncAttributeMaxDynamicSharedMemorySize,
                             SMEM_BYTES);
        cudaFuncSetAttribute(reduce_tail, cudaFuncAttributeMaxDynamicSharedMemorySize,
                             TAIL_SMEM_BYTES);
    }
    zero_kernel<<<4096, 256>>>();
    ft_kernel<<<grid_ft, 256, SMEM_BYTES>>>(xp, xo, W1p, W1o);
    reduce_tail<<<256, 256, TAIL_SMEM_BYTES>>>(b1p, b1o, W2, b2, W3, b3, Wo, bo,
                                               (float*)d_out);
    dummy_kernel<<<1, 32>>>();   // pads launch period to 4 so ncu (-s 5) lands on ft_kernel
}